// round 9
// baseline (speedup 1.0000x reference)
#include <cuda_runtime.h>
#include <math.h>

#define BB 64
#define QQ 4096
#define NN 256
#define NL 21
#define INF_REPLACE 1000000.0f

#define GD    8                      // bins per axis
#define NCELL (GD*GD*GD)             // 512
#define CELL  6.25f                  // 50/8, exactly representable
#define INV_CELL 0.16f               // 8/50
#define MARG  2.001f                 // 2m radius + fp32 boundary-rounding margin
#define CAP   16                     // targets per bin cell
#define RCAP  32                     // targets per reach list
#define QROWS 256

// ---- device scratch (static globals: allowed; no runtime allocation) ----
__device__ float4        g_tc[BB * NN];
__device__ int           g_cnt[BB * NCELL];
__device__ unsigned char g_bin[BB * NCELL * CAP];
__device__ int           g_rcnt[BB * NCELL];
__device__ unsigned char g_reach[BB * NCELL * RCAP];
__device__ int           g_ovf[BB];

// ---------------- Kernel 1: bin targets per (b, cell) ----------------------
__global__ __launch_bounds__(256) void bin_kernel(const float* __restrict__ tboxes)
{
    const int b = blockIdx.x, t = threadIdx.x;
    __shared__ float s_traw[NN * 6];
    __shared__ int   s_cnt[NCELL];
    __shared__ alignas(16) unsigned char s_bin[NCELL * CAP];
    __shared__ int   s_ovf;

    const float* tb = tboxes + (size_t)b * NN * 6;
    for (int i = t; i < NN * 6; i += 256) s_traw[i] = tb[i];
    for (int i = t; i < NCELL; i += 256) s_cnt[i] = 0;
    if (t == 0) s_ovf = 0;
    __syncthreads();

    const float x = s_traw[t*6+0], y = s_traw[t*6+1], z = s_traw[t*6+2];
    g_tc[b * NN + t] = make_float4(x, y, z, 0.0f);
    const int cx = min(GD-1, max(0, (int)(x * INV_CELL)));
    const int cy = min(GD-1, max(0, (int)(y * INV_CELL)));
    const int cz = min(GD-1, max(0, (int)(z * INV_CELL)));
    const int c  = (cz * GD + cy) * GD + cx;
    const int old = atomicAdd(&s_cnt[c], 1);
    if (old < CAP) s_bin[c * CAP + old] = (unsigned char)t;
    else           atomicExch(&s_ovf, 1);
    __syncthreads();

    for (int i = t; i < NCELL; i += 256) g_cnt[b * NCELL + i] = s_cnt[i];
    for (int i = t; i < NCELL * CAP / 4; i += 256)
        ((int*)(g_bin + (size_t)b * NCELL * CAP))[i] = ((const int*)s_bin)[i];
    if (t == 0) g_ovf[b] = s_ovf;
}

// ---------------- Kernel 2: build reach lists per (b, cell) -----------------
// reach[b][c] = all targets whose center lies in cell-box(c) expanded by MARG.
// Any q assigned (with fp32 rounding) to cell c lies within eps<1e-3 of the
// box, so every target with true dist<=2 of q is in the expanded box. Targets
// within MARG of a cell are at most one cell away, so scanning the 27
// neighborhood of bins finds them all.
__global__ __launch_bounds__(512) void reach_kernel()
{
    const int b = blockIdx.x, c = threadIdx.x;     // c = cell id, 512 threads
    __shared__ float4 s_tc[NN];
    __shared__ int    s_cnt[NCELL];
    __shared__ alignas(16) unsigned char s_bin[NCELL * CAP];

    for (int i = c; i < NN; i += 512) s_tc[i] = g_tc[b * NN + i];
    for (int i = c; i < NCELL; i += 512) s_cnt[i] = g_cnt[b * NCELL + i];
    for (int i = c; i < NCELL * CAP / 4; i += 512)
        ((int*)s_bin)[i] = ((const int*)(g_bin + (size_t)b * NCELL * CAP))[i];
    __syncthreads();

    const int cx = c & 7, cy = (c >> 3) & 7, cz = c >> 6;
    const float lox = cx * CELL - MARG, hix = cx * CELL + CELL + MARG;
    const float loy = cy * CELL - MARG, hiy = cy * CELL + CELL + MARG;
    const float loz = cz * CELL - MARG, hiz = cz * CELL + CELL + MARG;

    int r = 0, ov = 0;
    unsigned char* rl = g_reach + ((size_t)b * NCELL + c) * RCAP;
    for (int dz = -1; dz <= 1; dz++) {
        const int nz = cz + dz; if (nz < 0 || nz >= GD) continue;
        for (int dy = -1; dy <= 1; dy++) {
            const int ny = cy + dy; if (ny < 0 || ny >= GD) continue;
            for (int dx = -1; dx <= 1; dx++) {
                const int nx = cx + dx; if (nx < 0 || nx >= GD) continue;
                const int nc = (nz * GD + ny) * GD + nx;
                const int kc = min(s_cnt[nc], CAP);
                for (int k = 0; k < kc; k++) {
                    const int n = s_bin[nc * CAP + k];
                    const float4 tc = s_tc[n];
                    if (tc.x >= lox && tc.x <= hix &&
                        tc.y >= loy && tc.y <= hiy &&
                        tc.z >= loz && tc.z <= hiz) {
                        if (r < RCAP) rl[r++] = (unsigned char)n;
                        else ov = 1;
                    }
                }
            }
        }
    }
    g_rcnt[b * NCELL + c] = r;
    if (ov) atomicExch(&g_ovf[b], 1);
}

// ---------------- Kernel 3: stream INF_REPLACE ------------------------------
__global__ __launch_bounds__(256) void fill_kernel(float4* __restrict__ out)
{
    const float4 v = make_float4(INF_REPLACE, INF_REPLACE, INF_REPLACE, INF_REPLACE);
    const int n4 = BB * QQ * NN / 4;
    const int stride = gridDim.x * blockDim.x;
    #pragma unroll 8
    for (int i = blockIdx.x * blockDim.x + threadIdx.x; i < n4; i += stride)
        out[i] = v;
}

// ---------------- exact cost (reference arithmetic) -------------------------
__device__ __noinline__ float exact_cost(
    const float* __restrict__ logits, const int* __restrict__ labels,
    const float* __restrict__ tboxes,
    int b, int q, int n,
    float pcx, float pcy, float pcz,
    float psx, float psy, float psz, float dist)
{
    const float* tb = tboxes + ((size_t)b * NN + n) * 6;
    const float tcx = __ldg(tb + 0), tcy = __ldg(tb + 1), tcz = __ldg(tb + 2);
    const float tsx = __ldg(tb + 3), tsy = __ldg(tb + 4), tsz = __ldg(tb + 5);

    float ix = fminf(pcx + 0.5f*psx, tcx + 0.5f*tsx) - fmaxf(pcx - 0.5f*psx, tcx - 0.5f*tsx);
    float iy = fminf(pcy + 0.5f*psy, tcy + 0.5f*tsy) - fmaxf(pcy - 0.5f*psy, tcy - 0.5f*tsy);
    float iz = fminf(pcz + 0.5f*psz, tcz + 0.5f*tsz) - fmaxf(pcz - 0.5f*psz, tcz - 0.5f*tsz);
    ix = fmaxf(ix, 0.0f); iy = fmaxf(iy, 0.0f); iz = fmaxf(iz, 0.0f);

    const float inter = ix * iy * iz;
    const float vol1 = psx * psy * psz;
    const float vol2 = tsx * tsy * tsz;
    const float uni  = vol1 + vol2 - inter;
    const float iou  = (uni > 0.0f) ? (inter / uni) : 0.0f;

    const float* lg = logits + ((size_t)b * QQ + q) * NL;
    const int lbl = __ldg(labels + b * NN + n);
    float s = 0.0f, el = 0.0f;
    #pragma unroll
    for (int c = 0; c < NL; c++) {
        const float e = expf(__ldg(lg + c));
        s += e;
        if (c == lbl) el = e;
    }
    const float cls = -(el / s);
    return cls + 5.0f * dist + 2.0f * (1.0f - iou);
}

// ---------------- Kernel 4: fixup — one cell lookup per q-row ---------------
__global__ __launch_bounds__(256) void fixup_kernel(
    const float* __restrict__ logits,
    const float* __restrict__ pboxes,
    const int*   __restrict__ labels,
    const float* __restrict__ tboxes,
    float*       __restrict__ out)
{
    const int b  = blockIdx.y;
    const int q0 = blockIdx.x * QROWS;
    const int t  = threadIdx.x;

    __shared__ float4 s_tc[NN];
    __shared__ int    s_rcnt[NCELL];
    __shared__ alignas(16) unsigned char s_reach[NCELL * RCAP];
    __shared__ float  s_pb[QROWS * 6];
    __shared__ int    s_ovf;

    {
        const float* pb = pboxes + ((size_t)b * QQ + q0) * 6;
        for (int i = t; i < QROWS * 6; i += 256) s_pb[i] = pb[i];
    }
    for (int i = t; i < NN; i += 256) s_tc[i] = g_tc[b * NN + i];
    for (int i = t; i < NCELL; i += 256) s_rcnt[i] = g_rcnt[b * NCELL + i];
    {
        const int4* src = (const int4*)(g_reach + (size_t)b * NCELL * RCAP);
        for (int i = t; i < NCELL * RCAP / 16; i += 256) ((int4*)s_reach)[i] = src[i];
    }
    if (t == 0) s_ovf = g_ovf[b];
    __syncthreads();

    const float px  = s_pb[t*6+0], py  = s_pb[t*6+1], pz  = s_pb[t*6+2];
    const float psx = s_pb[t*6+3], psy = s_pb[t*6+4], psz = s_pb[t*6+5];
    const int q = q0 + t;

    if (s_ovf != 0) {
        // correctness fallback (practically never taken)
        for (int n = 0; n < NN; n++) {
            const float4 tc = s_tc[n];
            const float dx = px - tc.x, dy = py - tc.y, dz = pz - tc.z;
            const float dist = sqrtf(dx*dx + dy*dy + dz*dz);
            if (dist <= 2.0f)
                out[((size_t)b * QQ + q) * NN + n] =
                    exact_cost(logits, labels, tboxes, b, q, n,
                               px, py, pz, psx, psy, psz, dist);
        }
        return;
    }

    const int cx = min(GD-1, max(0, (int)(px * INV_CELL)));
    const int cy = min(GD-1, max(0, (int)(py * INV_CELL)));
    const int cz = min(GD-1, max(0, (int)(pz * INV_CELL)));
    const int c  = (cz * GD + cy) * GD + cx;

    const int cnt = s_rcnt[c];
    for (int k = 0; k < cnt; k++) {
        const int n = s_reach[c * RCAP + k];
        const float4 tc = s_tc[n];
        const float dx = px - tc.x, dy = py - tc.y, dz = pz - tc.z;
        const float dist = sqrtf(dx*dx + dy*dy + dz*dz);
        if (dist <= 2.0f)
            out[((size_t)b * QQ + q) * NN + n] =
                exact_cost(logits, labels, tboxes, b, q, n,
                           px, py, pz, psx, psy, psz, dist);
    }
}

extern "C" void kernel_launch(void* const* d_in, const int* in_sizes, int n_in,
                              void* d_out, int out_size)
{
    const float* logits = (const float*)d_in[0];  // [B,Q,21]
    const float* pboxes = (const float*)d_in[1];  // [B,Q,6]
    const int*   labels = (const int*)  d_in[2];  // [B,N]
    const float* tboxes = (const float*)d_in[3];  // [B,N,6]
    float*       out    = (float*)d_out;          // [B,Q,N]

    bin_kernel<<<BB, 256>>>(tboxes);
    reach_kernel<<<BB, 512>>>();
    fill_kernel<<<148 * 32, 256>>>((float4*)out);

    dim3 fgrid(QQ / QROWS, BB);                   // (16, 64)
    fixup_kernel<<<fgrid, 256>>>(logits, pboxes, labels, tboxes, out);
}

// round 10
// speedup vs baseline: 1.0882x; 1.0882x over previous
#include <cuda_runtime.h>
#include <math.h>

#define BB 64
#define QQ 4096
#define NN 256
#define NL 21
#define INF_REPLACE 1000000.0f

#define GD    8                      // bins per axis
#define NCELL (GD*GD*GD)             // 512
#define CELL  6.25f                  // 50/8, exactly representable
#define INV_CELL 0.16f               // 8/50
#define MARG  2.001f                 // 2m radius + fp32 boundary-rounding margin
#define CAP   16                     // targets per bin cell
#define RCAP  32                     // targets per reach list
#define QROWS 256

// ---- device scratch (static globals: allowed; no runtime allocation) ----
__device__ float4        g_tc[BB * NN];          // target centers (L2-hot, 1MB)
__device__ int           g_rcnt[BB * NCELL];
__device__ unsigned char g_reach[BB * NCELL * RCAP];
__device__ int           g_ovf[BB];

// ------- Kernel 1: bin targets AND build reach lists, one block per b -------
// reach[b][c] = targets whose center lies in cell-box(c) expanded by MARG.
// Any q assigned (with fp32 rounding) to cell c lies within eps<<1e-3 of the
// box, so every target with true dist<=2 of that q is in the expanded box.
// Expansion 2.001 < CELL, so such targets are at most 1 cell away -> the 27-
// neighborhood of bins finds them all.
__global__ __launch_bounds__(512) void setup_kernel(const float* __restrict__ tboxes)
{
    const int b = blockIdx.x, t = threadIdx.x;
    __shared__ float  s_traw[NN * 6];
    __shared__ float4 s_tc[NN];
    __shared__ int    s_cnt[NCELL];
    __shared__ unsigned char s_bin[NCELL * CAP];
    __shared__ int    s_ovf;

    const float* tb = tboxes + (size_t)b * NN * 6;
    for (int i = t; i < NN * 6; i += 512) s_traw[i] = tb[i];
    if (t < NCELL) s_cnt[t] = 0;
    if (t == 0) s_ovf = 0;
    __syncthreads();

    if (t < NN) {
        const float x = s_traw[t*6+0], y = s_traw[t*6+1], z = s_traw[t*6+2];
        const float4 tc4 = make_float4(x, y, z, 0.0f);
        s_tc[t] = tc4;
        g_tc[b * NN + t] = tc4;
        const int cx = min(GD-1, max(0, (int)(x * INV_CELL)));
        const int cy = min(GD-1, max(0, (int)(y * INV_CELL)));
        const int cz = min(GD-1, max(0, (int)(z * INV_CELL)));
        const int c  = (cz * GD + cy) * GD + cx;
        const int old = atomicAdd(&s_cnt[c], 1);
        if (old < CAP) s_bin[c * CAP + old] = (unsigned char)t;
        else           atomicExch(&s_ovf, 1);
    }
    __syncthreads();

    // thread t builds reach list for cell t
    const int c = t;
    const int cx = c & 7, cy = (c >> 3) & 7, cz = c >> 6;
    const float lox = cx * CELL - MARG, hix = cx * CELL + CELL + MARG;
    const float loy = cy * CELL - MARG, hiy = cy * CELL + CELL + MARG;
    const float loz = cz * CELL - MARG, hiz = cz * CELL + CELL + MARG;

    int r = 0, ov = 0;
    unsigned char* rl = g_reach + ((size_t)b * NCELL + c) * RCAP;
    for (int dz = -1; dz <= 1; dz++) {
        const int nz = cz + dz; if (nz < 0 || nz >= GD) continue;
        for (int dy = -1; dy <= 1; dy++) {
            const int ny = cy + dy; if (ny < 0 || ny >= GD) continue;
            for (int dx = -1; dx <= 1; dx++) {
                const int nx = cx + dx; if (nx < 0 || nx >= GD) continue;
                const int nc = (nz * GD + ny) * GD + nx;
                const int kc = min(s_cnt[nc], CAP);
                for (int k = 0; k < kc; k++) {
                    const int n = s_bin[nc * CAP + k];
                    const float4 tc = s_tc[n];
                    if (tc.x >= lox && tc.x <= hix &&
                        tc.y >= loy && tc.y <= hiy &&
                        tc.z >= loz && tc.z <= hiz) {
                        if (r < RCAP) rl[r++] = (unsigned char)n;
                        else ov = 1;
                    }
                }
            }
        }
    }
    g_rcnt[b * NCELL + c] = r;
    if (t == 0 || ov) g_ovf[b] = (s_ovf | ov);   // t==0 also clears when fine
    if (ov) atomicExch(&g_ovf[b], 1);
}

// ---------------- Kernel 2: stream INF_REPLACE ------------------------------
__global__ __launch_bounds__(256) void fill_kernel(float4* __restrict__ out)
{
    const float4 v = make_float4(INF_REPLACE, INF_REPLACE, INF_REPLACE, INF_REPLACE);
    const int n4 = BB * QQ * NN / 4;
    const int stride = gridDim.x * blockDim.x;
    #pragma unroll 8
    for (int i = blockIdx.x * blockDim.x + threadIdx.x; i < n4; i += stride)
        out[i] = v;
}

// ---------------- exact cost (reference arithmetic) -------------------------
__device__ __noinline__ float exact_cost(
    const float* __restrict__ logits, const int* __restrict__ labels,
    const float* __restrict__ tboxes,
    int b, int q, int n,
    float pcx, float pcy, float pcz,
    float psx, float psy, float psz, float dist)
{
    const float* tb = tboxes + ((size_t)b * NN + n) * 6;
    const float tcx = __ldg(tb + 0), tcy = __ldg(tb + 1), tcz = __ldg(tb + 2);
    const float tsx = __ldg(tb + 3), tsy = __ldg(tb + 4), tsz = __ldg(tb + 5);

    float ix = fminf(pcx + 0.5f*psx, tcx + 0.5f*tsx) - fmaxf(pcx - 0.5f*psx, tcx - 0.5f*tsx);
    float iy = fminf(pcy + 0.5f*psy, tcy + 0.5f*tsy) - fmaxf(pcy - 0.5f*psy, tcy - 0.5f*tsy);
    float iz = fminf(pcz + 0.5f*psz, tcz + 0.5f*tsz) - fmaxf(pcz - 0.5f*psz, tcz - 0.5f*tsz);
    ix = fmaxf(ix, 0.0f); iy = fmaxf(iy, 0.0f); iz = fmaxf(iz, 0.0f);

    const float inter = ix * iy * iz;
    const float vol1 = psx * psy * psz;
    const float vol2 = tsx * tsy * tsz;
    const float uni  = vol1 + vol2 - inter;
    const float iou  = (uni > 0.0f) ? (inter / uni) : 0.0f;

    const float* lg = logits + ((size_t)b * QQ + q) * NL;
    const int lbl = __ldg(labels + b * NN + n);
    float s = 0.0f, el = 0.0f;
    #pragma unroll
    for (int c = 0; c < NL; c++) {
        const float e = expf(__ldg(lg + c));
        s += e;
        if (c == lbl) el = e;
    }
    const float cls = -(el / s);
    return cls + 5.0f * dist + 2.0f * (1.0f - iou);
}

// ------ Kernel 3: fixup — no smem, no syncs, one q per thread ---------------
__global__ __launch_bounds__(256) void fixup_kernel(
    const float* __restrict__ logits,
    const float* __restrict__ pboxes,
    const int*   __restrict__ labels,
    const float* __restrict__ tboxes,
    float*       __restrict__ out)
{
    const int b = blockIdx.y;
    const int q = blockIdx.x * QROWS + threadIdx.x;

    const float* pb = pboxes + ((size_t)b * QQ + q) * 6;
    const float px  = __ldg(pb + 0);
    const float py  = __ldg(pb + 1);
    const float pz  = __ldg(pb + 2);
    const float psx = __ldg(pb + 3);
    const float psy = __ldg(pb + 4);
    const float psz = __ldg(pb + 5);

    if (__ldg(&g_ovf[b]) != 0) {
        // correctness fallback (practically never taken): scan all targets
        for (int n = 0; n < NN; n++) {
            const float4 tc = g_tc[b * NN + n];
            const float dx = px - tc.x, dy = py - tc.y, dz = pz - tc.z;
            const float dist = sqrtf(dx*dx + dy*dy + dz*dz);
            if (dist <= 2.0f)
                out[((size_t)b * QQ + q) * NN + n] =
                    exact_cost(logits, labels, tboxes, b, q, n,
                               px, py, pz, psx, psy, psz, dist);
        }
        return;
    }

    const int cx = min(GD-1, max(0, (int)(px * INV_CELL)));
    const int cy = min(GD-1, max(0, (int)(py * INV_CELL)));
    const int cz = min(GD-1, max(0, (int)(pz * INV_CELL)));
    const int c  = (cz * GD + cy) * GD + cx;

    const int cnt = __ldg(&g_rcnt[b * NCELL + c]);
    const unsigned char* rl = g_reach + ((size_t)b * NCELL + c) * RCAP;
    for (int k = 0; k < cnt; k++) {
        const int n = __ldg(rl + k);
        const float4 tc = g_tc[b * NN + n];
        const float dx = px - tc.x, dy = py - tc.y, dz = pz - tc.z;
        const float dist = sqrtf(dx*dx + dy*dy + dz*dz);
        if (dist <= 2.0f)
            out[((size_t)b * QQ + q) * NN + n] =
                exact_cost(logits, labels, tboxes, b, q, n,
                           px, py, pz, psx, psy, psz, dist);
    }
}

extern "C" void kernel_launch(void* const* d_in, const int* in_sizes, int n_in,
                              void* d_out, int out_size)
{
    const float* logits = (const float*)d_in[0];  // [B,Q,21]
    const float* pboxes = (const float*)d_in[1];  // [B,Q,6]
    const int*   labels = (const int*)  d_in[2];  // [B,N]
    const float* tboxes = (const float*)d_in[3];  // [B,N,6]
    float*       out    = (float*)d_out;          // [B,Q,N]

    setup_kernel<<<BB, 512>>>(tboxes);
    fill_kernel<<<148 * 32, 256>>>((float4*)out);

    dim3 fgrid(QQ / QROWS, BB);                   // (16, 64)
    fixup_kernel<<<fgrid, 256>>>(logits, pboxes, labels, tboxes, out);
}